// round 1
// baseline (speedup 1.0000x reference)
#include <cuda_runtime.h>
#include <cuda_bf16.h>

// ---------------------------------------------------------------------------
// OccNet folding decoder, fused.
//   coarse: x = relu(fea@W_l1+b_l1)@W_l2+b_l2            (8,1024,3)
//   fine:   feat=[grid2|point3|fea1024]; h=relu(feat@W_c1+b_c1)
//           h2=relu(h@W_c2+b_c2); fine=h2@W_c3+b_c3+point (8,16384,3)
// Key transform: feat@W_c1 collapses to fcon[b,c] (global part, precomputed)
// + 2 grid FMAs + 3 point FMAs per element. Dominant cost is conv2
// (34.4 G MACs) done with packed fma.rn.f32x2.
// ---------------------------------------------------------------------------

#define SMEM_BYTES (27648 * 4)   // h_sh 16384 + w_sh 8192 + ovl 3072 floats

__device__ float g_h1[8 * 1024];
__device__ float g_x[8 * 3072];
__device__ float g_fcon[8 * 512];

// ---- packed f32x2 helpers --------------------------------------------------
__device__ __forceinline__ unsigned long long pack2(float x) {
    unsigned long long r;
    asm("mov.b64 %0, {%1, %1};" : "=l"(r) : "f"(x));
    return r;
}
__device__ __forceinline__ void fma2(unsigned long long& d,
                                     unsigned long long a,
                                     unsigned long long b) {
    asm("fma.rn.f32x2 %0, %1, %2, %0;" : "+l"(d) : "l"(a), "l"(b));
}
__device__ __forceinline__ float2 unpack2(unsigned long long v) {
    float2 r;
    asm("mov.b64 {%0, %1}, %2;" : "=f"(r.x), "=f"(r.y) : "l"(v));
    return r;
}

// ---------------------------------------------------------------------------
// Small batched linear: out[b,n] = act(in[b,:] @ W[:,n] + bias[n]), B=8, K=1024
// ---------------------------------------------------------------------------
__global__ void lin8_kernel(const float* __restrict__ in,
                            const float* __restrict__ W,
                            const float* __restrict__ bias,
                            float* __restrict__ out,
                            float* __restrict__ out2,
                            int N, int relu, int K) {
    __shared__ float fs[8192];
    const int tid = threadIdx.x;
    for (int i = tid; i < 8 * K; i += 256) fs[i] = in[i];
    __syncthreads();
    const int n = blockIdx.x * 256 + tid;
    if (n >= N) return;
    float acc[8];
#pragma unroll
    for (int bb = 0; bb < 8; bb++) acc[bb] = 0.f;
#pragma unroll 4
    for (int k = 0; k < K; k++) {
        const float w = W[(size_t)k * N + n];
#pragma unroll
        for (int bb = 0; bb < 8; bb++) acc[bb] += fs[bb * K + k] * w;
    }
    const float bv = bias[n];
#pragma unroll
    for (int bb = 0; bb < 8; bb++) {
        float v = acc[bb] + bv;
        if (relu) v = fmaxf(v, 0.f);
        out[(size_t)bb * N + n] = v;
        if (out2) out2[(size_t)bb * N + n] = v;
    }
}

// ---------------------------------------------------------------------------
// Fused fine kernel. One block = 2 coarse points = 32 fine points (M=32).
// N=512 held fully in-block so conv3 (N-reduction) fuses; K=512 in 64 tiles
// of BK=8 with double-buffered W_c2 prefetch.
// Thread tile: tm = tid>>5 (M rows 4*tm..), tn = tid&31 (N cols 4*tn+128*j).
// ---------------------------------------------------------------------------
__global__ void __launch_bounds__(256)
fine_kernel(const float* __restrict__ xbuf,   // (8,3072) coarse points
            const float* __restrict__ fcon,   // (8,512) fea@W_c1[5:]+b_c1
            const float* __restrict__ W_c1,   // rows 0..4 used (grid/point)
            const float* __restrict__ W_c2,   // (512,512)
            const float* __restrict__ b_c2,
            const float* __restrict__ W_c3,   // (512,3)
            const float* __restrict__ b_c3,
            float* __restrict__ fine_out) {
    extern __shared__ float sm[];
    float* h_sh = sm;            // stage2: [k][m] 512x32 ; stage3/4: h2 [m][n] 32x512
    float* w_sh = sm + 16384;    // 2 x [8][512] W_c2 tiles
    float* ovl  = sm + 24576;    // stage1: W_c1 rows0-4 (2560) + fcon row (512); stage4: W_c3 (1536)

    const int tid = threadIdx.x;
    const int b   = blockIdx.x >> 9;
    const int p0  = (blockIdx.x & 511) << 1;

    // --- cooperative load of stage-1 constants -----------------------------
    {
        const float4* src1 = reinterpret_cast<const float4*>(W_c1);
        const float4* src2 = reinterpret_cast<const float4*>(fcon + b * 512);
        float4* dst = reinterpret_cast<float4*>(ovl);
        for (int f = tid; f < 768; f += 256)
            dst[f] = (f < 640) ? src1[f] : src2[f - 640];
    }
    // --- prefetch W_c2 tile 0 into registers -------------------------------
    float4 pf0, pf1, pf2, pf3;
    {
        const float4* wsrc = reinterpret_cast<const float4*>(W_c2);
        pf0 = wsrc[tid]; pf1 = wsrc[tid + 256];
        pf2 = wsrc[tid + 512]; pf3 = wsrc[tid + 768];
    }
    __syncthreads();

    // --- stage 1: h[c][m] = relu(fcon + grid + point contributions) --------
    {
        const int m  = tid & 31;
        const int wq = tid >> 5;
        const int p  = p0 + (m >> 4);
        const int g  = m & 15;
        const float step = 0.1f / 3.0f;
        const float gx = -0.05f + (float)(g & 3) * step;
        const float gy = -0.05f + (float)(g >> 2) * step;
        const float x0 = xbuf[(b * 1024 + p) * 3 + 0];
        const float x1 = xbuf[(b * 1024 + p) * 3 + 1];
        const float x2 = xbuf[(b * 1024 + p) * 3 + 2];
        const float* w0 = ovl;
        const float* w1 = ovl + 512;
        const float* w2 = ovl + 1024;
        const float* w3 = ovl + 1536;
        const float* w4 = ovl + 2048;
        const float* fc = ovl + 2560;
#pragma unroll 8
        for (int j = 0; j < 64; j++) {
            const int c = wq + (j << 3);
            float v = fc[c] + gx * w0[c] + gy * w1[c]
                    + x0 * w2[c] + x1 * w3[c] + x2 * w4[c];
            h_sh[c * 32 + m] = fmaxf(v, 0.f);
        }
    }
    __syncthreads();   // h ready; ovl reads done

    // store W_c2 tile 0, and repurpose ovl for W_c3
    {
        float4* wdst = reinterpret_cast<float4*>(w_sh);
        wdst[tid] = pf0; wdst[tid + 256] = pf1;
        wdst[tid + 512] = pf2; wdst[tid + 768] = pf3;
    }
    for (int i = tid; i < 1536; i += 256) ovl[i] = W_c3[i];
    __syncthreads();

    // --- stage 2: conv2 GEMM (M=32, N=512, K=512), packed f32x2 ------------
    const int tn = tid & 31;
    const int tm = tid >> 5;
    unsigned long long acc[4][4][2];
#pragma unroll
    for (int i = 0; i < 4; i++)
#pragma unroll
        for (int j = 0; j < 4; j++) { acc[i][j][0] = 0ull; acc[i][j][1] = 0ull; }

#pragma unroll 1
    for (int t = 0; t < 64; ++t) {
        if (t < 63) {
            const float4* wsrc = reinterpret_cast<const float4*>(W_c2 + (t + 1) * 4096);
            pf0 = wsrc[tid]; pf1 = wsrc[tid + 256];
            pf2 = wsrc[tid + 512]; pf3 = wsrc[tid + 768];
        }
        const float* wb = w_sh + (t & 1) * 4096;
#pragma unroll
        for (int kk = 0; kk < 8; ++kk) {
            const int k = t * 8 + kk;
            const float4 a4 = *reinterpret_cast<const float4*>(h_sh + k * 32 + 4 * tm);
            unsigned long long a2[4];
            a2[0] = pack2(a4.x); a2[1] = pack2(a4.y);
            a2[2] = pack2(a4.z); a2[3] = pack2(a4.w);
#pragma unroll
            for (int j = 0; j < 4; j++) {
                const ulonglong2 wv =
                    *reinterpret_cast<const ulonglong2*>(wb + kk * 512 + 4 * tn + 128 * j);
#pragma unroll
                for (int i = 0; i < 4; i++) {
                    fma2(acc[i][j][0], a2[i], wv.x);
                    fma2(acc[i][j][1], a2[i], wv.y);
                }
            }
        }
        __syncthreads();
        if (t < 63) {
            float4* wdst = reinterpret_cast<float4*>(w_sh + ((t + 1) & 1) * 4096);
            wdst[tid] = pf0; wdst[tid + 256] = pf1;
            wdst[tid + 512] = pf2; wdst[tid + 768] = pf3;
            __syncthreads();
        }
    }

    // --- stage 3: bias + relu, h2 -> shared as [m][512] --------------------
    float4 bc2v[4];
#pragma unroll
    for (int j = 0; j < 4; j++)
        bc2v[j] = *reinterpret_cast<const float4*>(b_c2 + 4 * tn + 128 * j);
#pragma unroll
    for (int i = 0; i < 4; i++) {
        const int m = 4 * tm + i;
#pragma unroll
        for (int j = 0; j < 4; j++) {
            const float2 lo = unpack2(acc[i][j][0]);
            const float2 hi = unpack2(acc[i][j][1]);
            float4 v;
            v.x = fmaxf(lo.x + bc2v[j].x, 0.f);
            v.y = fmaxf(lo.y + bc2v[j].y, 0.f);
            v.z = fmaxf(hi.x + bc2v[j].z, 0.f);
            v.w = fmaxf(hi.y + bc2v[j].w, 0.f);
            *reinterpret_cast<float4*>(h_sh + m * 512 + 4 * tn + 128 * j) = v;
        }
    }
    __syncthreads();

    // --- stage 4: conv3 (512->3) + bias + center, warp reductions ----------
    const int lane = tid & 31;
    const int warp = tid >> 5;
#pragma unroll 1
    for (int o = 0; o < 12; ++o) {
        const int oo = warp * 12 + o;      // 0..95 = 32 m * 3 j
        const int m = oo / 3;
        const int j = oo - m * 3;
        float s = 0.f;
#pragma unroll
        for (int q = 0; q < 16; q++) {
            const int n = lane + 32 * q;
            s += h_sh[m * 512 + n] * ovl[n * 3 + j];
        }
        s += __shfl_down_sync(0xffffffffu, s, 16);
        s += __shfl_down_sync(0xffffffffu, s, 8);
        s += __shfl_down_sync(0xffffffffu, s, 4);
        s += __shfl_down_sync(0xffffffffu, s, 2);
        s += __shfl_down_sync(0xffffffffu, s, 1);
        if (lane == 0) {
            const int p = p0 + (m >> 4);
            const int g = m & 15;
            const float center = xbuf[(b * 1024 + p) * 3 + j];
            fine_out[((size_t)b * 16384 + p * 16 + g) * 3 + j] = s + b_c3[j] + center;
        }
    }
}

// ---------------------------------------------------------------------------
extern "C" void kernel_launch(void* const* d_in, const int* in_sizes, int n_in,
                              void* d_out, int out_size) {
    const float* fea  = (const float*)d_in[0];
    const float* W_l1 = (const float*)d_in[1];
    const float* b_l1 = (const float*)d_in[2];
    const float* W_l2 = (const float*)d_in[3];
    const float* b_l2 = (const float*)d_in[4];
    const float* W_c1 = (const float*)d_in[5];
    const float* b_c1 = (const float*)d_in[6];
    const float* W_c2 = (const float*)d_in[7];
    const float* b_c2 = (const float*)d_in[8];
    const float* W_c3 = (const float*)d_in[9];
    const float* b_c3 = (const float*)d_in[10];

    float* out = (float*)d_out;
    float* xout = nullptr;
    float* fineout = out;
    if (out_size >= 24576 + 393216) {   // x (8*1024*3) then fine (8*16384*3)
        xout = out;
        fineout = out + 24576;
    }

    float *h1p, *xp, *fcp;
    cudaGetSymbolAddress((void**)&h1p, g_h1);
    cudaGetSymbolAddress((void**)&xp, g_x);
    cudaGetSymbolAddress((void**)&fcp, g_fcon);
    cudaFuncSetAttribute(fine_kernel,
                         cudaFuncAttributeMaxDynamicSharedMemorySize, SMEM_BYTES);

    // coarse branch + fcon precompute
    lin8_kernel<<<4, 256>>>(fea, W_l1, b_l1, h1p, nullptr, 1024, 1, 1024);
    lin8_kernel<<<2, 256>>>(fea, W_c1 + 5 * 512, b_c1, fcp, nullptr, 512, 0, 1024);
    lin8_kernel<<<12, 256>>>(h1p, W_l2, b_l2, xp, xout, 3072, 0, 1024);

    // fused fine branch: 8 batches * 512 (pairs of coarse points)
    fine_kernel<<<4096, 256, SMEM_BYTES>>>(xp, fcp, W_c1, W_c2, b_c2,
                                           W_c3, b_c3, fineout);
}

// round 7
// speedup vs baseline: 1.5638x; 1.5638x over previous
#include <cuda_runtime.h>
#include <cuda_bf16.h>
#include <cstdint>

// ===========================================================================
// OccNet folding decoder. conv2 (131072x512x512) as 3x-bf16-split GEMM on
// mma.sync HMMA (tcgen05 is unavailable: harness compiles at base sm_103).
// ===========================================================================

// ---------------- device scratch ----------------
__device__ float g_h1[8 * 1024];
__device__ float g_x[8 * 3072];
__device__ float g_fcon[8 * 512];
__device__ __nv_bfloat16 g_Hh[131072ull * 512];
__device__ __nv_bfloat16 g_Hl[131072ull * 512];
__device__ __nv_bfloat16 g_Wh[512 * 512];   // W_c2 transposed [N][K], hi split
__device__ __nv_bfloat16 g_Wl[512 * 512];   // lo split
__device__ float g_S[4][131072 * 3];        // conv3 partials per N-block

// ---------------- helpers ----------------
__device__ __forceinline__ uint32_t smem_u32(const void* p) {
    uint32_t a;
    asm("{ .reg .u64 t; cvta.to.shared.u64 t, %1; cvt.u32.u64 %0, t; }"
        : "=r"(a) : "l"(p));
    return a;
}

#define SW128(o) ((o) ^ (((o) >> 3) & 0x70))

#define CP_ASYNC16(dst, src) \
    asm volatile("cp.async.cg.shared.global [%0], [%1], 16;" :: "r"(dst), "l"(src) : "memory")
#define CP_COMMIT() asm volatile("cp.async.commit_group;" ::: "memory")

#define LDSM4(r0, r1, r2, r3, addr) \
    asm volatile("ldmatrix.sync.aligned.m8n8.x4.shared.b16 {%0,%1,%2,%3}, [%4];" \
                 : "=r"(r0), "=r"(r1), "=r"(r2), "=r"(r3) : "r"(addr))

#define MMA_BF16(c, a, b0, b1) \
    asm volatile("mma.sync.aligned.m16n8k16.row.col.f32.bf16.bf16.f32 " \
                 "{%0,%1,%2,%3}, {%4,%5,%6,%7}, {%8,%9}, {%0,%1,%2,%3};" \
                 : "+f"((c)[0]), "+f"((c)[1]), "+f"((c)[2]), "+f"((c)[3]) \
                 : "r"((a)[0]), "r"((a)[1]), "r"((a)[2]), "r"((a)[3]), \
                   "r"(b0), "r"(b1))

// ===========================================================================
// Small batched linear (validated in round 1):
// out[b,n] = act(in[b,:] @ W[:,n] + bias[n]), B=8, K elems of in per batch.
// ===========================================================================
__global__ void lin8_kernel(const float* __restrict__ in,
                            const float* __restrict__ W,
                            const float* __restrict__ bias,
                            float* __restrict__ out,
                            float* __restrict__ out2,
                            int N, int relu, int K) {
    __shared__ float fs[8192];
    const int tid = threadIdx.x;
    for (int i = tid; i < 8 * K; i += 256) fs[i] = in[i];
    __syncthreads();
    const int n = blockIdx.x * 256 + tid;
    if (n >= N) return;
    float acc[8];
#pragma unroll
    for (int bb = 0; bb < 8; bb++) acc[bb] = 0.f;
#pragma unroll 4
    for (int k = 0; k < K; k++) {
        const float w = W[(size_t)k * N + n];
#pragma unroll
        for (int bb = 0; bb < 8; bb++) acc[bb] += fs[bb * K + k] * w;
    }
    const float bv = bias[n];
#pragma unroll
    for (int bb = 0; bb < 8; bb++) {
        float v = acc[bb] + bv;
        if (relu) v = fmaxf(v, 0.f);
        out[(size_t)bb * N + n] = v;
        if (out2) out2[(size_t)bb * N + n] = v;
    }
}

// ===========================================================================
// Weight prep: transpose W_c2[K=512][N=512] -> [N][K], split to bf16 hi/lo.
// ===========================================================================
__global__ void wprep_kernel(const float* __restrict__ W) {
    __shared__ float ts[32][33];
    const int n0 = blockIdx.x * 32, k0 = blockIdx.y * 32;
    const int tx = threadIdx.x, ty = threadIdx.y;
#pragma unroll
    for (int r = 0; r < 32; r += 8)
        ts[ty + r][tx] = W[(size_t)(k0 + ty + r) * 512 + n0 + tx];
    __syncthreads();
#pragma unroll
    for (int r = 0; r < 32; r += 8) {
        const int n = n0 + ty + r, k = k0 + tx;
        const float w = ts[tx][ty + r];
        const __nv_bfloat16 wh = __float2bfloat16(w);
        const __nv_bfloat16 wl = __float2bfloat16(w - __bfloat162float(wh));
        g_Wh[(size_t)n * 512 + k] = wh;
        g_Wl[(size_t)n * 512 + k] = wl;
    }
}

// ===========================================================================
// P1: stage-1 collapse -> H = relu(fcon + grid/point FMAs), split Hh/Hl.
// One block per coarse point (16 fine rows x 512 ch); 2 channels/thread
// packed as bf16x2 for coalesced 4B stores.
// ===========================================================================
__global__ void __launch_bounds__(256)
p1_kernel(const float* __restrict__ W_c1) {
    __shared__ float ws[2560];
    __shared__ float fc[512];
    const int tid = threadIdx.x;
    const int p = blockIdx.x;            // global coarse point 0..8191
    const int b = p >> 10;
    for (int i = tid; i < 2560; i += 256) ws[i] = W_c1[i];
    for (int i = tid; i < 512; i += 256) fc[i] = g_fcon[b * 512 + i];
    const float x0 = g_x[p * 3 + 0];
    const float x1 = g_x[p * 3 + 1];
    const float x2 = g_x[p * 3 + 2];
    __syncthreads();
    const float step = 0.1f / 3.0f;
    uint32_t* Hh32 = reinterpret_cast<uint32_t*>(g_Hh);
    uint32_t* Hl32 = reinterpret_cast<uint32_t*>(g_Hl);
#pragma unroll 4
    for (int idx = tid; idx < 4096; idx += 256) {
        const int m = idx >> 8;              // fine row in point (0..15)
        const int c = (idx & 255) << 1;      // channel pair
        const float gx = -0.05f + (float)(m & 3) * step;
        const float gy = -0.05f + (float)(m >> 2) * step;
        uint32_t hhp = 0, hlp = 0;
#pragma unroll
        for (int u = 0; u < 2; u++) {
            const int cc = c + u;
            float v = fc[cc] + gx * ws[cc] + gy * ws[512 + cc]
                    + x0 * ws[1024 + cc] + x1 * ws[1536 + cc] + x2 * ws[2048 + cc];
            v = fmaxf(v, 0.f);
            const __nv_bfloat16 hh = __float2bfloat16(v);
            const __nv_bfloat16 hl = __float2bfloat16(v - __bfloat162float(hh));
            hhp |= (uint32_t)__bfloat16_as_ushort(hh) << (u * 16);
            hlp |= (uint32_t)__bfloat16_as_ushort(hl) << (u * 16);
        }
        const size_t row = ((size_t)p << 4) + m;
        Hh32[(row << 8) + (c >> 1)] = hhp;
        Hl32[(row << 8) + (c >> 1)] = hlp;
    }
}

// ===========================================================================
// conv2 GEMM on HMMA: CTA 128(M) x 128(N), BK=64, 3-stage cp.async pipeline,
// 3 bf16 terms (AhBh + AlBh + AhBl) into one fp32 accumulator.
// Epilogue: bias + relu + conv3 partial dot over this CTA's 128 N-cols.
// ===========================================================================
#define STAGE_BYTES 65536            // Ah 16K | Al 16K | Bh 16K | Bl 16K
#define SMEM_MAIN  (3 * STAGE_BYTES) // 192 KB
#define G_SMEM     (SMEM_MAIN + 8192)

__global__ void __launch_bounds__(256, 1)
gemm_kernel(const float* __restrict__ b_c2, const float* __restrict__ W_c3) {
    extern __shared__ __align__(1024) char sm[];
    const uint32_t sbase = smem_u32(sm);
    const int tid = threadIdx.x;
    const int nb = blockIdx.x;           // N block 0..3
    const int n0 = nb << 7;
    const int row0 = blockIdx.y << 7;    // M block * 128

    float* b2s = (float*)(sm + SMEM_MAIN);          // 128 f
    float* w3s = (float*)(sm + SMEM_MAIN + 512);    // 384 f
    float* psum = (float*)(sm + SMEM_MAIN + 2048);  // [4][128][3] f

    if (tid < 128) b2s[tid] = b_c2[n0 + tid];
    for (int i = tid; i < 384; i += 256) w3s[i] = W_c3[n0 * 3 + i];

    const int lane = tid & 31, warp = tid >> 5;
    const int wm = warp >> 2, wn = warp & 3;        // 2 x 4 warp grid

    // stage loader: 16 cp.async(16B) per thread
    auto load_stage = [&](int s, int c) {
        const uint32_t buf = sbase + s * STAGE_BYTES;
        const int k0 = c << 6;
#pragma unroll
        for (int t = 0; t < 8; t++) {               // A: Ah|Al
            const int i = (t << 8) + tid;           // 0..2047
            const int sp = i >> 10, rr = (i >> 3) & 127, q = i & 7;
            const __nv_bfloat16* src =
                (sp ? g_Hl : g_Hh) + (((size_t)(row0 + rr)) << 9) + k0 + (q << 3);
            CP_ASYNC16(buf + (sp << 14) + SW128((rr << 7) + (q << 4)), src);
        }
#pragma unroll
        for (int t = 0; t < 8; t++) {               // B: Bh|Bl
            const int i = (t << 8) + tid;
            const int sp = i >> 10, nn = (i >> 3) & 127, q = i & 7;
            const __nv_bfloat16* src =
                (sp ? g_Wl : g_Wh) + (((size_t)(n0 + nn)) << 9) + k0 + (q << 3);
            CP_ASYNC16(buf + 32768 + (sp << 14) + SW128((nn << 7) + (q << 4)), src);
        }
        CP_COMMIT();
    };

    float acc[4][4][4];
#pragma unroll
    for (int i = 0; i < 4; i++)
#pragma unroll
        for (int j = 0; j < 4; j++)
#pragma unroll
            for (int c = 0; c < 4; c++) acc[i][j][c] = 0.f;

    // per-lane ldmatrix base offsets (row*128, swizzle xor)
    const uint32_t lxor = (uint32_t)(lane & 7) << 4;
    uint32_t arow[4], brow[2];
#pragma unroll
    for (int i = 0; i < 4; i++) arow[i] = (uint32_t)((wm * 64 + i * 16 + (lane & 15)) << 7);
#pragma unroll
    for (int jj = 0; jj < 2; jj++) brow[jj] = (uint32_t)((wn * 32 + jj * 16 + (lane & 15)) << 7);

    load_stage(0, 0);
    load_stage(1, 1);

#pragma unroll 1
    for (int c = 0; c < 8; ++c) {
        if (c < 6) asm volatile("cp.async.wait_group 1;" ::: "memory");
        else       asm volatile("cp.async.wait_group 0;" ::: "memory");
        __syncthreads();
        if (c + 2 < 8) load_stage((c + 2) % 3, c + 2);

        const uint32_t sa = sbase + (uint32_t)(c % 3) * STAGE_BYTES;
        const uint32_t sb = sa + 32768;
#pragma unroll
        for (int t = 0; t < 4; ++t) {
            const uint32_t koff = ((uint32_t)t << 5) + (((uint32_t)lane >> 4) << 4);
            const uint32_t ks = koff ^ lxor;
            uint32_t ah[4][4], al[4][4], bh[2][4], bl[2][4];
#pragma unroll
            for (int i = 0; i < 4; i++) {
                LDSM4(ah[i][0], ah[i][1], ah[i][2], ah[i][3], sa + arow[i] + ks);
                LDSM4(al[i][0], al[i][1], al[i][2], al[i][3], sa + 16384 + arow[i] + ks);
            }
#pragma unroll
            for (int jj = 0; jj < 2; jj++) {
                LDSM4(bh[jj][0], bh[jj][1], bh[jj][2], bh[jj][3], sb + brow[jj] + ks);
                LDSM4(bl[jj][0], bl[jj][1], bl[jj][2], bl[jj][3], sb + 16384 + brow[jj] + ks);
            }
            // x4 B regs: frag n(0-7) -> {r0, r2}; n(8-15) -> {r1, r3}
#pragma unroll
            for (int i = 0; i < 4; i++)
#pragma unroll
                for (int jj = 0; jj < 2; jj++) {
                    MMA_BF16(acc[i][2 * jj],     ah[i], bh[jj][0], bh[jj][2]);
                    MMA_BF16(acc[i][2 * jj + 1], ah[i], bh[jj][1], bh[jj][3]);
                }
#pragma unroll
            for (int i = 0; i < 4; i++)
#pragma unroll
                for (int jj = 0; jj < 2; jj++) {
                    MMA_BF16(acc[i][2 * jj],     al[i], bh[jj][0], bh[jj][2]);
                    MMA_BF16(acc[i][2 * jj + 1], al[i], bh[jj][1], bh[jj][3]);
                }
#pragma unroll
            for (int i = 0; i < 4; i++)
#pragma unroll
                for (int jj = 0; jj < 2; jj++) {
                    MMA_BF16(acc[i][2 * jj],     ah[i], bl[jj][0], bl[jj][2]);
                    MMA_BF16(acc[i][2 * jj + 1], ah[i], bl[jj][1], bl[jj][3]);
                }
        }
        __syncthreads();
    }

    // ---- epilogue: bias + relu + conv3 partials over 128 cols -------------
    // acc frag (i,j): rows wm*64+i*16 + lane/4 + {0,8};
    //                 cols wn*32 + j*8 + (lane%4)*2 + {0,1}
#pragma unroll
    for (int i = 0; i < 4; i++) {
        float s0x = 0.f, s0y = 0.f, s0z = 0.f;
        float s1x = 0.f, s1y = 0.f, s1z = 0.f;
#pragma unroll
        for (int j = 0; j < 4; j++) {
            const int colb = wn * 32 + j * 8 + (lane & 3) * 2;
#pragma unroll
            for (int cc = 0; cc < 4; cc++) {
                const int col = colb + (cc & 1);
                const float v = fmaxf(acc[i][j][cc] + b2s[col], 0.f);
                const float w0 = w3s[col * 3 + 0];
                const float w1 = w3s[col * 3 + 1];
                const float w2 = w3s[col * 3 + 2];
                if (cc < 2) { s0x += v * w0; s0y += v * w1; s0z += v * w2; }
                else        { s1x += v * w0; s1y += v * w1; s1z += v * w2; }
            }
        }
#pragma unroll
        for (int d = 1; d < 4; d <<= 1) {
            s0x += __shfl_xor_sync(0xffffffffu, s0x, d);
            s0y += __shfl_xor_sync(0xffffffffu, s0y, d);
            s0z += __shfl_xor_sync(0xffffffffu, s0z, d);
            s1x += __shfl_xor_sync(0xffffffffu, s1x, d);
            s1y += __shfl_xor_sync(0xffffffffu, s1y, d);
            s1z += __shfl_xor_sync(0xffffffffu, s1z, d);
        }
        if ((lane & 3) == 0) {
            const int r = wm * 64 + i * 16 + (lane >> 2);
            psum[(wn * 128 + r) * 3 + 0] = s0x;
            psum[(wn * 128 + r) * 3 + 1] = s0y;
            psum[(wn * 128 + r) * 3 + 2] = s0z;
            psum[(wn * 128 + r + 8) * 3 + 0] = s1x;
            psum[(wn * 128 + r + 8) * 3 + 1] = s1y;
            psum[(wn * 128 + r + 8) * 3 + 2] = s1z;
        }
    }
    __syncthreads();
    if (tid < 128) {
#pragma unroll
        for (int j = 0; j < 3; j++) {
            g_S[nb][(size_t)(row0 + tid) * 3 + j] =
                psum[(0 * 128 + tid) * 3 + j] + psum[(1 * 128 + tid) * 3 + j] +
                psum[(2 * 128 + tid) * 3 + j] + psum[(3 * 128 + tid) * 3 + j];
        }
    }
}

// ===========================================================================
// Combine: fine = sum of 4 N-block partials + b_c3 + center
// ===========================================================================
__global__ void combine_kernel(const float* __restrict__ b_c3,
                               float* __restrict__ fine_out) {
    const int i = blockIdx.x * 256 + threadIdx.x;
    if (i >= 131072 * 3) return;
    const int r = i / 3;
    const int j = i - r * 3;
    fine_out[i] = g_S[0][i] + g_S[1][i] + g_S[2][i] + g_S[3][i]
                + b_c3[j] + g_x[(r >> 4) * 3 + j];
}

// ===========================================================================
extern "C" void kernel_launch(void* const* d_in, const int* in_sizes, int n_in,
                              void* d_out, int out_size) {
    const float* fea  = (const float*)d_in[0];
    const float* W_l1 = (const float*)d_in[1];
    const float* b_l1 = (const float*)d_in[2];
    const float* W_l2 = (const float*)d_in[3];
    const float* b_l2 = (const float*)d_in[4];
    const float* W_c1 = (const float*)d_in[5];
    const float* b_c1 = (const float*)d_in[6];
    const float* W_c2 = (const float*)d_in[7];
    const float* b_c2 = (const float*)d_in[8];
    const float* W_c3 = (const float*)d_in[9];
    const float* b_c3 = (const float*)d_in[10];

    float* out = (float*)d_out;
    float* xout = nullptr;
    float* fineout = out;
    if (out_size >= 24576 + 393216) {   // x (8*1024*3) then fine (8*16384*3)
        xout = out;
        fineout = out + 24576;
    }

    float *h1p, *xp, *fcp;
    cudaGetSymbolAddress((void**)&h1p, g_h1);
    cudaGetSymbolAddress((void**)&xp, g_x);
    cudaGetSymbolAddress((void**)&fcp, g_fcon);
    cudaFuncSetAttribute(gemm_kernel,
                         cudaFuncAttributeMaxDynamicSharedMemorySize, G_SMEM);

    // coarse branch + conv1 collapse (validated round-1 kernels)
    lin8_kernel<<<4, 256>>>(fea, W_l1, b_l1, h1p, nullptr, 1024, 1, 1024);
    lin8_kernel<<<2, 256>>>(fea, W_c1 + 5 * 512, b_c1, fcp, nullptr, 512, 0, 1024);
    lin8_kernel<<<12, 256>>>(h1p, W_l2, b_l2, xp, xout, 3072, 0, 1024);

    // weight transpose+split, H production
    wprep_kernel<<<dim3(16, 16), dim3(32, 8)>>>(W_c2);
    p1_kernel<<<8192, 256>>>(W_c1);

    // conv2 HMMA GEMM: n-blocks fastest so A rows are L2-shared
    gemm_kernel<<<dim3(4, 1024), 256, G_SMEM>>>(b_c2, W_c3);

    // conv3 partials + bias + center
    combine_kernel<<<1536, 256>>>(b_c3, fineout);
}

// round 9
// speedup vs baseline: 4.1347x; 2.6440x over previous
#include <cuda_runtime.h>
#include <cuda_bf16.h>
#include <cuda_fp16.h>
#include <cstdint>

// ===========================================================================
// OccNet folding decoder. conv2 (131072x512x512) as single-term fp16 HMMA
// GEMM (mma.sync m16n8k16). Error budget: fp16 rounding of A and B gives
// ~3e-4 L2-norm rel err vs 1e-3 threshold (calibrated on round-7 bf16 data).
// ===========================================================================

// ---------------- device scratch ----------------
__device__ float g_h1[8 * 1024];
__device__ float g_x[8 * 3072];
__device__ float g_fcon[8 * 512];
__device__ __half g_H[131072ull * 512];     // fp16 H (stage-1 output)
__device__ __half g_W[512 * 512];           // W_c2 transposed [N][K], fp16
__device__ float g_S[4][131072 * 3];        // conv3 partials per N-block

// ---------------- helpers ----------------
__device__ __forceinline__ uint32_t smem_u32(const void* p) {
    uint32_t a;
    asm("{ .reg .u64 t; cvta.to.shared.u64 t, %1; cvt.u32.u64 %0, t; }"
        : "=r"(a) : "l"(p));
    return a;
}

#define SW128(o) ((o) ^ (((o) >> 3) & 0x70))

#define CP_ASYNC16(dst, src) \
    asm volatile("cp.async.cg.shared.global [%0], [%1], 16;" :: "r"(dst), "l"(src) : "memory")
#define CP_COMMIT() asm volatile("cp.async.commit_group;" ::: "memory")

#define LDSM4(r0, r1, r2, r3, addr) \
    asm volatile("ldmatrix.sync.aligned.m8n8.x4.shared.b16 {%0,%1,%2,%3}, [%4];" \
                 : "=r"(r0), "=r"(r1), "=r"(r2), "=r"(r3) : "r"(addr))

#define MMA_F16(c, a, b0, b1) \
    asm volatile("mma.sync.aligned.m16n8k16.row.col.f32.f16.f16.f32 " \
                 "{%0,%1,%2,%3}, {%4,%5,%6,%7}, {%8,%9}, {%0,%1,%2,%3};" \
                 : "+f"((c)[0]), "+f"((c)[1]), "+f"((c)[2]), "+f"((c)[3]) \
                 : "r"((a)[0]), "r"((a)[1]), "r"((a)[2]), "r"((a)[3]), \
                   "r"(b0), "r"(b1))

// ===========================================================================
// Small batched linear, 4-way intra-block k-split:
// out[b,n] = act(in[b,:] @ W[:,n] + bias[n]), B=8, K=1024, 64 cols/block.
// ===========================================================================
__global__ void __launch_bounds__(256)
lin8b_kernel(const float* __restrict__ in, const float* __restrict__ W,
             const float* __restrict__ bias, float* __restrict__ out,
             float* __restrict__ out2, int N, int K, int relu) {
    __shared__ float fs[8192];
    __shared__ float part[2048];
    const int tid = threadIdx.x;
    for (int i = tid; i < 8 * K; i += 256) fs[i] = in[i];
    __syncthreads();
    const int nl = tid & 63;
    const int kq = tid >> 6;
    const int n = blockIdx.x * 64 + nl;
    const int KS = K >> 2;
    float acc[8];
#pragma unroll
    for (int b = 0; b < 8; b++) acc[b] = 0.f;
    const int k0 = kq * KS;
#pragma unroll 4
    for (int k = k0; k < k0 + KS; k++) {
        const float w = W[(size_t)k * N + n];
#pragma unroll
        for (int b = 0; b < 8; b++) acc[b] += fs[b * K + k] * w;
    }
#pragma unroll
    for (int b = 0; b < 8; b++) part[((kq * 8 + b) << 6) | nl] = acc[b];
    __syncthreads();
    if (kq == 0) {
        const float bv = bias[n];
#pragma unroll
        for (int b = 0; b < 8; b++) {
            float v = part[(b << 6) | nl] + part[((8 + b) << 6) | nl]
                    + part[((16 + b) << 6) | nl] + part[((24 + b) << 6) | nl] + bv;
            if (relu) v = fmaxf(v, 0.f);
            out[(size_t)b * N + n] = v;
            if (out2) out2[(size_t)b * N + n] = v;
        }
    }
}

// ===========================================================================
// Weight prep: transpose W_c2[K=512][N=512] -> fp16 [N][K].
// ===========================================================================
__global__ void wprep_kernel(const float* __restrict__ W) {
    __shared__ float ts[32][33];
    const int n0 = blockIdx.x * 32, k0 = blockIdx.y * 32;
    const int tx = threadIdx.x, ty = threadIdx.y;
#pragma unroll
    for (int r = 0; r < 32; r += 8)
        ts[ty + r][tx] = W[(size_t)(k0 + ty + r) * 512 + n0 + tx];
    __syncthreads();
#pragma unroll
    for (int r = 0; r < 32; r += 8) {
        const int n = n0 + ty + r, k = k0 + tx;
        g_W[(size_t)n * 512 + k] = __float2half(ts[tx][ty + r]);
    }
}

// ===========================================================================
// P1: stage-1 collapse -> H = relu(fcon + grid/point FMAs), fp16.
// One block per coarse point (16 fine rows x 512 ch), paired 4B stores.
// ===========================================================================
__global__ void __launch_bounds__(256)
p1_kernel(const float* __restrict__ W_c1) {
    __shared__ float ws[2560];
    __shared__ float fc[512];
    const int tid = threadIdx.x;
    const int p = blockIdx.x;            // global coarse point 0..8191
    const int b = p >> 10;
    for (int i = tid; i < 2560; i += 256) ws[i] = W_c1[i];
    for (int i = tid; i < 512; i += 256) fc[i] = g_fcon[b * 512 + i];
    const float x0 = g_x[p * 3 + 0];
    const float x1 = g_x[p * 3 + 1];
    const float x2 = g_x[p * 3 + 2];
    __syncthreads();
    const float step = 0.1f / 3.0f;
    uint32_t* H32 = reinterpret_cast<uint32_t*>(g_H);
#pragma unroll 4
    for (int idx = tid; idx < 4096; idx += 256) {
        const int m = idx >> 8;              // fine row in point (0..15)
        const int c = (idx & 255) << 1;      // channel pair
        const float gx = -0.05f + (float)(m & 3) * step;
        const float gy = -0.05f + (float)(m >> 2) * step;
        uint32_t hp = 0;
#pragma unroll
        for (int u = 0; u < 2; u++) {
            const int cc = c + u;
            float v = fc[cc] + gx * ws[cc] + gy * ws[512 + cc]
                    + x0 * ws[1024 + cc] + x1 * ws[1536 + cc] + x2 * ws[2048 + cc];
            v = fmaxf(v, 0.f);
            hp |= (uint32_t)__half_as_ushort(__float2half(v)) << (u * 16);
        }
        const size_t row = ((size_t)p << 4) + m;
        H32[(row << 8) + (c >> 1)] = hp;
    }
}

// ===========================================================================
// conv2 GEMM on fp16 HMMA: CTA 128(M) x 128(N), BK=64, 4-stage cp.async.
// Epilogue: bias + relu + conv3 partial dot over this CTA's 128 N-cols.
// ===========================================================================
#define STAGE_BYTES 32768            // A 16K | B 16K
#define SMEM_MAIN  (4 * STAGE_BYTES) // 128 KB
#define G_SMEM     (SMEM_MAIN + 8192)

__global__ void __launch_bounds__(256, 1)
gemm_kernel(const float* __restrict__ b_c2, const float* __restrict__ W_c3) {
    extern __shared__ __align__(1024) char sm[];
    const uint32_t sbase = smem_u32(sm);
    const int tid = threadIdx.x;
    const int nb = blockIdx.x;           // N block 0..3
    const int n0 = nb << 7;
    const int row0 = blockIdx.y << 7;    // M block * 128

    float* b2s = (float*)(sm + SMEM_MAIN);          // 128 f
    float* w3s = (float*)(sm + SMEM_MAIN + 512);    // 384 f
    float* psum = (float*)(sm + SMEM_MAIN + 2048);  // [4][128][3] f

    if (tid < 128) b2s[tid] = b_c2[n0 + tid];
    for (int i = tid; i < 384; i += 256) w3s[i] = W_c3[n0 * 3 + i];

    const int lane = tid & 31, warp = tid >> 5;
    const int wm = warp >> 2, wn = warp & 3;        // 2 x 4 warp grid

    // stage loader: 8 cp.async(16B) per thread
    auto load_stage = [&](int s, int c) {
        const uint32_t buf = sbase + s * STAGE_BYTES;
        const int k0 = c << 6;
#pragma unroll
        for (int t = 0; t < 4; t++) {               // A
            const int i = (t << 8) + tid;           // 0..1023
            const int rr = i >> 3, q = i & 7;
            const __half* src = g_H + (((size_t)(row0 + rr)) << 9) + k0 + (q << 3);
            CP_ASYNC16(buf + SW128((rr << 7) + (q << 4)), src);
        }
#pragma unroll
        for (int t = 0; t < 4; t++) {               // B
            const int i = (t << 8) + tid;
            const int nn = i >> 3, q = i & 7;
            const __half* src = g_W + (((size_t)(n0 + nn)) << 9) + k0 + (q << 3);
            CP_ASYNC16(buf + 16384 + SW128((nn << 7) + (q << 4)), src);
        }
        CP_COMMIT();
    };

    float acc[4][4][4];
#pragma unroll
    for (int i = 0; i < 4; i++)
#pragma unroll
        for (int j = 0; j < 4; j++)
#pragma unroll
            for (int c = 0; c < 4; c++) acc[i][j][c] = 0.f;

    // per-lane ldmatrix base offsets (row*128, swizzle xor from row&7==lane&7)
    const uint32_t lxor = (uint32_t)(lane & 7) << 4;
    uint32_t arow[4], brow[2];
#pragma unroll
    for (int i = 0; i < 4; i++) arow[i] = (uint32_t)((wm * 64 + i * 16 + (lane & 15)) << 7);
#pragma unroll
    for (int jj = 0; jj < 2; jj++) brow[jj] = (uint32_t)((wn * 32 + jj * 16 + (lane & 15)) << 7);

    load_stage(0, 0);
    load_stage(1, 1);
    load_stage(2, 2);

#pragma unroll 1
    for (int c = 0; c < 8; ++c) {
        if (c < 6)      asm volatile("cp.async.wait_group 2;" ::: "memory");
        else if (c == 6) asm volatile("cp.async.wait_group 1;" ::: "memory");
        else             asm volatile("cp.async.wait_group 0;" ::: "memory");
        __syncthreads();
        if (c + 3 < 8) load_stage((c + 3) & 3, c + 3);

        const uint32_t sa = sbase + (uint32_t)(c & 3) * STAGE_BYTES;
        const uint32_t sb = sa + 16384;
#pragma unroll
        for (int t = 0; t < 4; ++t) {
            const uint32_t koff = ((uint32_t)t << 5) + (((uint32_t)lane >> 4) << 4);
            const uint32_t ks = koff ^ lxor;
            uint32_t ah[4][4], bh[2][4];
#pragma unroll
            for (int i = 0; i < 4; i++)
                LDSM4(ah[i][0], ah[i][1], ah[i][2], ah[i][3], sa + arow[i] + ks);
#pragma unroll
            for (int jj = 0; jj < 2; jj++)
                LDSM4(bh[jj][0], bh[jj][1], bh[jj][2], bh[jj][3], sb + brow[jj] + ks);
            // x4 B regs: frag n(0-7) -> {r0, r2}; n(8-15) -> {r1, r3}
#pragma unroll
            for (int i = 0; i < 4; i++)
#pragma unroll
                for (int jj = 0; jj < 2; jj++) {
                    MMA_F16(acc[i][2 * jj],     ah[i], bh[jj][0], bh[jj][2]);
                    MMA_F16(acc[i][2 * jj + 1], ah[i], bh[jj][1], bh[jj][3]);
                }
        }
        __syncthreads();
    }

    // ---- epilogue: bias + relu + conv3 partials over 128 cols -------------
    // acc frag (i,j): rows wm*64+i*16 + lane/4 + {0,8};
    //                 cols wn*32 + j*8 + (lane%4)*2 + {0,1}
#pragma unroll
    for (int i = 0; i < 4; i++) {
        float s0x = 0.f, s0y = 0.f, s0z = 0.f;
        float s1x = 0.f, s1y = 0.f, s1z = 0.f;
#pragma unroll
        for (int j = 0; j < 4; j++) {
            const int colb = wn * 32 + j * 8 + (lane & 3) * 2;
#pragma unroll
            for (int cc = 0; cc < 4; cc++) {
                const int col = colb + (cc & 1);
                const float v = fmaxf(acc[i][j][cc] + b2s[col], 0.f);
                const float w0 = w3s[col * 3 + 0];
                const float w1 = w3s[col * 3 + 1];
                const float w2 = w3s[col * 3 + 2];
                if (cc < 2) { s0x += v * w0; s0y += v * w1; s0z += v * w2; }
                else        { s1x += v * w0; s1y += v * w1; s1z += v * w2; }
            }
        }
#pragma unroll
        for (int d = 1; d < 4; d <<= 1) {
            s0x += __shfl_xor_sync(0xffffffffu, s0x, d);
            s0y += __shfl_xor_sync(0xffffffffu, s0y, d);
            s0z += __shfl_xor_sync(0xffffffffu, s0z, d);
            s1x += __shfl_xor_sync(0xffffffffu, s1x, d);
            s1y += __shfl_xor_sync(0xffffffffu, s1y, d);
            s1z += __shfl_xor_sync(0xffffffffu, s1z, d);
        }
        if ((lane & 3) == 0) {
            const int r = wm * 64 + i * 16 + (lane >> 2);
            psum[(wn * 128 + r) * 3 + 0] = s0x;
            psum[(wn * 128 + r) * 3 + 1] = s0y;
            psum[(wn * 128 + r) * 3 + 2] = s0z;
            psum[(wn * 128 + r + 8) * 3 + 0] = s1x;
            psum[(wn * 128 + r + 8) * 3 + 1] = s1y;
            psum[(wn * 128 + r + 8) * 3 + 2] = s1z;
        }
    }
    __syncthreads();
    if (tid < 128) {
#pragma unroll
        for (int j = 0; j < 3; j++) {
            g_S[nb][(size_t)(row0 + tid) * 3 + j] =
                psum[(0 * 128 + tid) * 3 + j] + psum[(1 * 128 + tid) * 3 + j] +
                psum[(2 * 128 + tid) * 3 + j] + psum[(3 * 128 + tid) * 3 + j];
        }
    }
}

// ===========================================================================
// Combine: fine = sum of 4 N-block partials + b_c3 + center
// ===========================================================================
__global__ void combine_kernel(const float* __restrict__ b_c3,
                               float* __restrict__ fine_out) {
    const int i = blockIdx.x * 256 + threadIdx.x;
    if (i >= 131072 * 3) return;
    const int r = i / 3;
    const int j = i - r * 3;
    fine_out[i] = g_S[0][i] + g_S[1][i] + g_S[2][i] + g_S[3][i]
                + b_c3[j] + g_x[(r >> 4) * 3 + j];
}

// ===========================================================================
extern "C" void kernel_launch(void* const* d_in, const int* in_sizes, int n_in,
                              void* d_out, int out_size) {
    const float* fea  = (const float*)d_in[0];
    const float* W_l1 = (const float*)d_in[1];
    const float* b_l1 = (const float*)d_in[2];
    const float* W_l2 = (const float*)d_in[3];
    const float* b_l2 = (const float*)d_in[4];
    const float* W_c1 = (const float*)d_in[5];
    const float* b_c1 = (const float*)d_in[6];
    const float* W_c2 = (const float*)d_in[7];
    const float* b_c2 = (const float*)d_in[8];
    const float* W_c3 = (const float*)d_in[9];
    const float* b_c3 = (const float*)d_in[10];

    float* out = (float*)d_out;
    float* xout = nullptr;
    float* fineout = out;
    if (out_size >= 24576 + 393216) {   // x (8*1024*3) then fine (8*16384*3)
        xout = out;
        fineout = out + 24576;
    }

    float *h1p, *xp, *fcp;
    cudaGetSymbolAddress((void**)&h1p, g_h1);
    cudaGetSymbolAddress((void**)&xp, g_x);
    cudaGetSymbolAddress((void**)&fcp, g_fcon);
    cudaFuncSetAttribute(gemm_kernel,
                         cudaFuncAttributeMaxDynamicSharedMemorySize, G_SMEM);

    // coarse branch + conv1 collapse
    lin8b_kernel<<<16, 256>>>(fea, W_l1, b_l1, h1p, nullptr, 1024, 1024, 1);
    lin8b_kernel<<<8, 256>>>(fea, W_c1 + 5 * 512, b_c1, fcp, nullptr, 512, 1024, 0);
    lin8b_kernel<<<48, 256>>>(h1p, W_l2, b_l2, xp, xout, 3072, 1024, 0);

    // weight transpose (fp16), H production (fp16)
    wprep_kernel<<<dim3(16, 16), dim3(32, 8)>>>(W_c2);
    p1_kernel<<<8192, 256>>>(W_c1);

    // conv2 fp16 HMMA GEMM: n-blocks fastest so A rows are L2-shared
    gemm_kernel<<<dim3(4, 1024), 256, G_SMEM>>>(b_c2, W_c3);

    // conv3 partials + bias + center
    combine_kernel<<<1536, 256>>>(b_c3, fineout);
}

// round 10
// speedup vs baseline: 5.3292x; 1.2889x over previous
#include <cuda_runtime.h>
#include <cuda_bf16.h>
#include <cuda_fp16.h>
#include <cstdint>

// ===========================================================================
// OccNet folding decoder. conv2 (131072x512x512) as single-term fp16 HMMA
// GEMM (mma.sync m16n8k16), 3-stage cp.async pipeline at occupancy 2.
// ===========================================================================

// ---------------- device scratch ----------------
__device__ float g_h1[8 * 1024];
__device__ float g_x[8 * 3072];
__device__ float g_fcon[8 * 512];
__device__ __half g_H[131072ull * 512];     // fp16 H (stage-1 output)
__device__ __half g_W[512 * 512];           // W_c2 transposed [N][K], fp16
__device__ float g_S[4][131072 * 3];        // conv3 partials per N-block

// ---------------- helpers ----------------
__device__ __forceinline__ uint32_t smem_u32(const void* p) {
    uint32_t a;
    asm("{ .reg .u64 t; cvta.to.shared.u64 t, %1; cvt.u32.u64 %0, t; }"
        : "=r"(a) : "l"(p));
    return a;
}

#define SW128(o) ((o) ^ (((o) >> 3) & 0x70))

#define CP_ASYNC16(dst, src) \
    asm volatile("cp.async.cg.shared.global [%0], [%1], 16;" :: "r"(dst), "l"(src) : "memory")
#define CP_COMMIT() asm volatile("cp.async.commit_group;" ::: "memory")

#define LDSM4(r0, r1, r2, r3, addr) \
    asm volatile("ldmatrix.sync.aligned.m8n8.x4.shared.b16 {%0,%1,%2,%3}, [%4];" \
                 : "=r"(r0), "=r"(r1), "=r"(r2), "=r"(r3) : "r"(addr))

#define MMA_F16(c, a, b0, b1) \
    asm volatile("mma.sync.aligned.m16n8k16.row.col.f32.f16.f16.f32 " \
                 "{%0,%1,%2,%3}, {%4,%5,%6,%7}, {%8,%9}, {%0,%1,%2,%3};" \
                 : "+f"((c)[0]), "+f"((c)[1]), "+f"((c)[2]), "+f"((c)[3]) \
                 : "r"((a)[0]), "r"((a)[1]), "r"((a)[2]), "r"((a)[3]), \
                   "r"(b0), "r"(b1))

// ===========================================================================
// Fused small linears over fea (K=1024, B=8):
//   blocks 0..15 : h1[b,n]   = relu(fea @ W_l1 + b_l1), N=1024
//   blocks 16..23: fcon[b,n] = fea @ W_c1[5:,:] + b_c1,  N=512
// 4-way intra-block k-split, 64 cols/block.
// ===========================================================================
__global__ void __launch_bounds__(256)
linA_kernel(const float* __restrict__ fea,
            const float* __restrict__ W_l1, const float* __restrict__ b_l1,
            const float* __restrict__ W_c1c, const float* __restrict__ b_c1,
            float* __restrict__ h1, float* __restrict__ fcon) {
    __shared__ float fs[8192];
    __shared__ float part[2048];
    const int tid = threadIdx.x;
    for (int i = tid; i < 8192; i += 256) fs[i] = fea[i];
    __syncthreads();
    const int nl = tid & 63;
    const int kq = tid >> 6;
    const bool is1 = blockIdx.x < 16;
    const int N = is1 ? 1024 : 512;
    const int n = (is1 ? blockIdx.x : blockIdx.x - 16) * 64 + nl;
    const float* W = is1 ? W_l1 : W_c1c;
    float acc[8];
#pragma unroll
    for (int b = 0; b < 8; b++) acc[b] = 0.f;
    const int k0 = kq << 8;
#pragma unroll 4
    for (int k = k0; k < k0 + 256; k++) {
        const float w = W[(size_t)k * N + n];
#pragma unroll
        for (int b = 0; b < 8; b++) acc[b] += fs[(b << 10) + k] * w;
    }
#pragma unroll
    for (int b = 0; b < 8; b++) part[((kq * 8 + b) << 6) | nl] = acc[b];
    __syncthreads();
    if (kq == 0) {
        const float bv = is1 ? b_l1[n] : b_c1[n];
        float* out = is1 ? h1 : fcon;
#pragma unroll
        for (int b = 0; b < 8; b++) {
            float v = part[(b << 6) | nl] + part[((8 + b) << 6) | nl]
                    + part[((16 + b) << 6) | nl] + part[((24 + b) << 6) | nl] + bv;
            if (is1) v = fmaxf(v, 0.f);
            out[(size_t)b * N + n] = v;
        }
    }
}

// ===========================================================================
// lin2: x[b,n] = h1[b,:] @ W_l2 + b_l2, N=3072, K=1024 (writes x + xout copy)
// ===========================================================================
__global__ void __launch_bounds__(256)
lin2_kernel(const float* __restrict__ in, const float* __restrict__ W,
            const float* __restrict__ bias, float* __restrict__ out,
            float* __restrict__ out2) {
    __shared__ float fs[8192];
    __shared__ float part[2048];
    const int tid = threadIdx.x;
    for (int i = tid; i < 8192; i += 256) fs[i] = in[i];
    __syncthreads();
    const int nl = tid & 63;
    const int kq = tid >> 6;
    const int n = blockIdx.x * 64 + nl;
    float acc[8];
#pragma unroll
    for (int b = 0; b < 8; b++) acc[b] = 0.f;
    const int k0 = kq << 8;
#pragma unroll 4
    for (int k = k0; k < k0 + 256; k++) {
        const float w = W[(size_t)k * 3072 + n];
#pragma unroll
        for (int b = 0; b < 8; b++) acc[b] += fs[(b << 10) + k] * w;
    }
#pragma unroll
    for (int b = 0; b < 8; b++) part[((kq * 8 + b) << 6) | nl] = acc[b];
    __syncthreads();
    if (kq == 0) {
        const float bv = bias[n];
#pragma unroll
        for (int b = 0; b < 8; b++) {
            float v = part[(b << 6) | nl] + part[((8 + b) << 6) | nl]
                    + part[((16 + b) << 6) | nl] + part[((24 + b) << 6) | nl] + bv;
            out[(size_t)b * 3072 + n] = v;
            if (out2) out2[(size_t)b * 3072 + n] = v;
        }
    }
}

// ===========================================================================
// Weight prep: transpose W_c2[K=512][N=512] -> fp16 [N][K].
// ===========================================================================
__global__ void wprep_kernel(const float* __restrict__ W) {
    __shared__ float ts[32][33];
    const int n0 = blockIdx.x * 32, k0 = blockIdx.y * 32;
    const int tx = threadIdx.x, ty = threadIdx.y;
#pragma unroll
    for (int r = 0; r < 32; r += 8)
        ts[ty + r][tx] = W[(size_t)(k0 + ty + r) * 512 + n0 + tx];
    __syncthreads();
#pragma unroll
    for (int r = 0; r < 32; r += 8) {
        const int n = n0 + ty + r, k = k0 + tx;
        g_W[(size_t)n * 512 + k] = __float2half(ts[tx][ty + r]);
    }
}

// ===========================================================================
// P1: stage-1 collapse -> H = relu(fcon + grid/point FMAs), fp16, 8B stores.
// One block per coarse point (16 fine rows x 512 ch).
// ===========================================================================
__global__ void __launch_bounds__(256)
p1_kernel(const float* __restrict__ W_c1) {
    __shared__ float ws[2560];
    __shared__ float fc[512];
    const int tid = threadIdx.x;
    const int p = blockIdx.x;            // global coarse point 0..8191
    const int b = p >> 10;
    for (int i = tid; i < 2560; i += 256) ws[i] = W_c1[i];
    for (int i = tid; i < 512; i += 256) fc[i] = g_fcon[b * 512 + i];
    const float x0 = g_x[p * 3 + 0];
    const float x1 = g_x[p * 3 + 1];
    const float x2 = g_x[p * 3 + 2];
    __syncthreads();
    const float step = 0.1f / 3.0f;
    uint2* H64 = reinterpret_cast<uint2*>(g_H);
#pragma unroll
    for (int idx = tid; idx < 2048; idx += 256) {
        const int m = idx >> 7;              // fine row in point (0..15)
        const int c = (idx & 127) << 2;      // channel quad
        const float gx = -0.05f + (float)(m & 3) * step;
        const float gy = -0.05f + (float)(m >> 2) * step;
        uint32_t lo = 0, hi = 0;
#pragma unroll
        for (int u = 0; u < 4; u++) {
            const int cc = c + u;
            float v = fc[cc] + gx * ws[cc] + gy * ws[512 + cc]
                    + x0 * ws[1024 + cc] + x1 * ws[1536 + cc] + x2 * ws[2048 + cc];
            v = fmaxf(v, 0.f);
            const uint32_t bits = (uint32_t)__half_as_ushort(__float2half(v));
            if (u < 2) lo |= bits << (u * 16);
            else       hi |= bits << ((u - 2) * 16);
        }
        const size_t row = ((size_t)p << 4) + m;
        H64[(row << 7) + (c >> 2)] = make_uint2(lo, hi);
    }
}

// ===========================================================================
// conv2 GEMM on fp16 HMMA: CTA 128(M) x 128(N), BK=64, 3-stage cp.async,
// occupancy 2, single __syncthreads per chunk.
// Epilogue: bias + relu + conv3 partial dot over this CTA's 128 N-cols.
// ===========================================================================
#define STAGE_BYTES 32768            // A 16K | B 16K
#define NSTAGE 3
#define SMEM_MAIN  (NSTAGE * STAGE_BYTES)   // 96 KB
#define G_SMEM     (SMEM_MAIN + 8704)       // + b2s/w3s/psum

__global__ void __launch_bounds__(256, 2)
gemm_kernel(const float* __restrict__ b_c2, const float* __restrict__ W_c3) {
    extern __shared__ __align__(1024) char sm[];
    const uint32_t sbase = smem_u32(sm);
    const int tid = threadIdx.x;
    const int nb = blockIdx.x;           // N block 0..3
    const int n0 = nb << 7;
    const int row0 = blockIdx.y << 7;    // M block * 128

    float* b2s = (float*)(sm + SMEM_MAIN);          // 128 f
    float* w3s = (float*)(sm + SMEM_MAIN + 512);    // 384 f
    float* psum = (float*)(sm + SMEM_MAIN + 2048);  // [4][128][3] f = 6144 B

    if (tid < 128) b2s[tid] = b_c2[n0 + tid];
    for (int i = tid; i < 384; i += 256) w3s[i] = W_c3[n0 * 3 + i];

    const int lane = tid & 31, warp = tid >> 5;
    const int wm = warp >> 2, wn = warp & 3;        // 2 x 4 warp grid

    // stage loader: 8 cp.async(16B) per thread
    auto load_stage = [&](int s, int c) {
        const uint32_t buf = sbase + s * STAGE_BYTES;
        const int k0 = c << 6;
#pragma unroll
        for (int t = 0; t < 4; t++) {               // A
            const int i = (t << 8) + tid;           // 0..1023
            const int rr = i >> 3, q = i & 7;
            const __half* src = g_H + (((size_t)(row0 + rr)) << 9) + k0 + (q << 3);
            CP_ASYNC16(buf + SW128((rr << 7) + (q << 4)), src);
        }
#pragma unroll
        for (int t = 0; t < 4; t++) {               // B
            const int i = (t << 8) + tid;
            const int nn = i >> 3, q = i & 7;
            const __half* src = g_W + (((size_t)(n0 + nn)) << 9) + k0 + (q << 3);
            CP_ASYNC16(buf + 16384 + SW128((nn << 7) + (q << 4)), src);
        }
        CP_COMMIT();
    };

    float acc[4][4][4];
#pragma unroll
    for (int i = 0; i < 4; i++)
#pragma unroll
        for (int j = 0; j < 4; j++)
#pragma unroll
            for (int c = 0; c < 4; c++) acc[i][j][c] = 0.f;

    // per-lane ldmatrix base offsets (row*128, swizzle xor from row&7)
    const uint32_t lxor = (uint32_t)(lane & 7) << 4;
    uint32_t arow[4], brow[2];
#pragma unroll
    for (int i = 0; i < 4; i++) arow[i] = (uint32_t)((wm * 64 + i * 16 + (lane & 15)) << 7);
#pragma unroll
    for (int jj = 0; jj < 2; jj++) brow[jj] = (uint32_t)((wn * 32 + jj * 16 + (lane & 15)) << 7);

    load_stage(0, 0);
    load_stage(1, 1);

#pragma unroll 1
    for (int c = 0; c < 8; ++c) {
        // stages c, c+1 committed ahead; wait until stage c is resident.
        if (c < 7) asm volatile("cp.async.wait_group 1;" ::: "memory");
        else       asm volatile("cp.async.wait_group 0;" ::: "memory");
        __syncthreads();   // also orders prior-iter reads before next write
        if (c + 2 < 8) load_stage((c + 2) % NSTAGE, c + 2);

        const uint32_t sa = sbase + (uint32_t)(c % NSTAGE) * STAGE_BYTES;
        const uint32_t sb = sa + 16384;
#pragma unroll
        for (int t = 0; t < 4; ++t) {
            const uint32_t koff = ((uint32_t)t << 5) + (((uint32_t)lane >> 4) << 4);
            const uint32_t ks = koff ^ lxor;
            uint32_t ah[4][4], bh[2][4];
#pragma unroll
            for (int i = 0; i < 4; i++)
                LDSM4(ah[i][0], ah[i][1], ah[i][2], ah[i][3], sa + arow[i] + ks);
#pragma unroll
            for (int jj = 0; jj < 2; jj++)
                LDSM4(bh[jj][0], bh[jj][1], bh[jj][2], bh[jj][3], sb + brow[jj] + ks);
            // x4 B regs: frag n(0-7) -> {r0, r2}; n(8-15) -> {r1, r3}
#pragma unroll
            for (int i = 0; i < 4; i++)
#pragma unroll
                for (int jj = 0; jj < 2; jj++) {
                    MMA_F16(acc[i][2 * jj],     ah[i], bh[jj][0], bh[jj][2]);
                    MMA_F16(acc[i][2 * jj + 1], ah[i], bh[jj][1], bh[jj][3]);
                }
        }
    }
    __syncthreads();

    // ---- epilogue: bias + relu + conv3 partials over 128 cols -------------
    // acc frag (i,j): rows wm*64+i*16 + lane/4 + {0,8};
    //                 cols wn*32 + j*8 + (lane%4)*2 + {0,1}
#pragma unroll
    for (int i = 0; i < 4; i++) {
        float s0x = 0.f, s0y = 0.f, s0z = 0.f;
        float s1x = 0.f, s1y = 0.f, s1z = 0.f;
#pragma unroll
        for (int j = 0; j < 4; j++) {
            const int colb = wn * 32 + j * 8 + (lane & 3) * 2;
#pragma unroll
            for (int cc = 0; cc < 4; cc++) {
                const int col = colb + (cc & 1);
                const float v = fmaxf(acc[i][j][cc] + b2s[col], 0.f);
                const float w0 = w3s[col * 3 + 0];
                const float w1 = w3s[col * 3 + 1];
                const float w2 = w3s[col * 3 + 2];
                if (cc < 2) { s0x += v * w0; s0y += v * w1; s0z += v * w2; }
                else        { s1x += v * w0; s1y += v * w1; s1z += v * w2; }
            }
        }
#pragma unroll
        for (int d = 1; d < 4; d <<= 1) {
            s0x += __shfl_xor_sync(0xffffffffu, s0x, d);
            s0y += __shfl_xor_sync(0xffffffffu, s0y, d);
            s0z += __shfl_xor_sync(0xffffffffu, s0z, d);
            s1x += __shfl_xor_sync(0xffffffffu, s1x, d);
            s1y += __shfl_xor_sync(0xffffffffu, s1y, d);
            s1z += __shfl_xor_sync(0xffffffffu, s1z, d);
        }
        if ((lane & 3) == 0) {
            const int r = wm * 64 + i * 16 + (lane >> 2);
            psum[(wn * 128 + r) * 3 + 0] = s0x;
            psum[(wn * 128 + r) * 3 + 1] = s0y;
            psum[(wn * 128 + r) * 3 + 2] = s0z;
            psum[(wn * 128 + r + 8) * 3 + 0] = s1x;
            psum[(wn * 128 + r + 8) * 3 + 1] = s1y;
            psum[(wn * 128 + r + 8) * 3 + 2] = s1z;
        }
    }
    __syncthreads();
    if (tid < 128) {
#pragma unroll
        for (int j = 0; j < 3; j++) {
            g_S[nb][(size_t)(row0 + tid) * 3 + j] =
                psum[(0 * 128 + tid) * 3 + j] + psum[(1 * 128 + tid) * 3 + j] +
                psum[(2 * 128 + tid) * 3 + j] + psum[(3 * 128 + tid) * 3 + j];
        }
    }
}

// ===========================================================================
// Combine: fine = sum of 4 N-block partials + b_c3 + center
// ===========================================================================
__global__ void combine_kernel(const float* __restrict__ b_c3,
                               float* __restrict__ fine_out) {
    const int i = blockIdx.x * 256 + threadIdx.x;
    if (i >= 131072 * 3) return;
    const int r = i / 3;
    const int j = i - r * 3;
    fine_out[i] = g_S[0][i] + g_S[1][i] + g_S[2][i] + g_S[3][i]
                + b_c3[j] + g_x[(r >> 4) * 3 + j];
}

// ===========================================================================
extern "C" void kernel_launch(void* const* d_in, const int* in_sizes, int n_in,
                              void* d_out, int out_size) {
    const float* fea  = (const float*)d_in[0];
    const float* W_l1 = (const float*)d_in[1];
    const float* b_l1 = (const float*)d_in[2];
    const float* W_l2 = (const float*)d_in[3];
    const float* b_l2 = (const float*)d_in[4];
    const float* W_c1 = (const float*)d_in[5];
    const float* b_c1 = (const float*)d_in[6];
    const float* W_c2 = (const float*)d_in[7];
    const float* b_c2 = (const float*)d_in[8];
    const float* W_c3 = (const float*)d_in[9];
    const float* b_c3 = (const float*)d_in[10];

    float* out = (float*)d_out;
    float* xout = nullptr;
    float* fineout = out;
    if (out_size >= 24576 + 393216) {   // x (8*1024*3) then fine (8*16384*3)
        xout = out;
        fineout = out + 24576;
    }

    float *h1p, *xp, *fcp;
    cudaGetSymbolAddress((void**)&h1p, g_h1);
    cudaGetSymbolAddress((void**)&xp, g_x);
    cudaGetSymbolAddress((void**)&fcp, g_fcon);
    cudaFuncSetAttribute(gemm_kernel,
                         cudaFuncAttributeMaxDynamicSharedMemorySize, G_SMEM);

    // independent weight transpose first
    wprep_kernel<<<dim3(16, 16), dim3(32, 8)>>>(W_c2);

    // coarse branch: fused lin1+fcon, then lin2
    linA_kernel<<<24, 256>>>(fea, W_l1, b_l1, W_c1 + 5 * 512, b_c1, h1p, fcp);
    lin2_kernel<<<48, 256>>>(h1p, W_l2, b_l2, xp, xout);

    // H production (fp16)
    p1_kernel<<<8192, 256>>>(W_c1);

    // conv2 fp16 HMMA GEMM: n-blocks fastest so A rows are L2-shared
    gemm_kernel<<<dim3(4, 1024), 256, G_SMEM>>>(b_c2, W_c3);

    // conv3 partials + bias + center
    combine_kernel<<<1536, 256>>>(b_c3, fineout);
}